// round 5
// baseline (speedup 1.0000x reference)
#include <cuda_runtime.h>
#include <math.h>

// Problem constants (fixed shapes from setup_inputs)
#define BB  8
#define CC  192
#define HH  56
#define WW  56
#define NN  3136            // H*W
#define CC2 384             // 2*C
#define CG  96              // C2/4
#define KNB 9               // K_NEIGHBORS
#define NT  25              // column tiles (3200/128)
#define BNEPS 1e-5f

// ---------------- scratch (static device globals; no runtime alloc) --------
__device__ float d_pe  [NN * CC];                         //  2.4 MB
__device__ float d_rel [(size_t)NN * NN + 64];            // 39.3 MB (+pad)
__device__ float d_h   [(size_t)BB * NN * CC];            // 19.3 MB
__device__ float d_xn  [(size_t)BB * NN * CC];            // 19.3 MB
__device__ float d_sq  [BB * NN];
__device__ float d_cv  [(size_t)NT * BB * NN * KNB];      // 22.6 MB candidate values
__device__ int   d_ci  [(size_t)NT * BB * NN * KNB];      // 22.6 MB candidate indices
__device__ int   d_nn  [BB * NN * KNB];
__device__ float d_gbuf[(size_t)BB * NN * CC2];           // 38.6 MB
__device__ float d_ybuf[(size_t)BB * NN * CC2];           // 38.6 MB
__device__ float d_obuf[(size_t)BB * NN * CC];            // 19.3 MB

// ---------------- positional embedding -------------------------------------
__global__ void pe_kernel() {
    int i = blockIdx.x * blockDim.x + threadIdx.x;
    if (i >= NN * CC) return;
    int n = i / CC, k = i % CC;
    int yy = n / WW, xx = n % WW;
    float pos = (k < 96) ? (float)yy : (float)xx;
    int kk = k % 96;                       // within emb_h or emb_w
    int oi = (kk < 48) ? kk : kk - 48;     // omega index
    float omega = expf(-logf(10000.0f) * (float)oi / 48.0f);
    float ang = pos * omega;
    d_pe[i] = (kk < 48) ? sinf(ang) : cosf(ang);
}

// ---------------- 128x128x16 double-buffered SGEMM with mode epilogues ------
// C(m,n) = sum_k A(m,k) * B(n,k)
// MODE 0: fc1   A = x_b (stored KxM), epilogue bias+BN1 -> d_h
// MODE 1: rel   A=B=d_pe, upper-tri tiles only (lower triangle never read)
// MODE 2: dist  A=B=d_xn_b, SYMMETRIC upper-tri; fused per-tile top-9 -> cand
// MODE 3: group A = d_gbuf slice, B = gc_w[g], bias+BN+GELU -> d_ybuf
// MODE 4: fc2   A = d_ybuf (all batches), bias+BN2 -> d_obuf
template <int MODE>
__global__ void __launch_bounds__(256, 2)
gemm_kernel(const float* __restrict__ Ain, const float* __restrict__ Bin,
            const float* __restrict__ q0, const float* __restrict__ q1,
            const float* __restrict__ q2, const float* __restrict__ q3,
            const float* __restrict__ q4)
{
    // symmetric modes: only upper-triangle tiles (ti <= tj)
    if ((MODE == 1 || MODE == 2) && blockIdx.y > blockIdx.x) return;

    int M, Nc, K, lda, ldb;
    const float* A;
    const float* B;
    const int bz = blockIdx.z;

    if (MODE == 0) {           // fc1 (A stored K x M)
        A = Ain + (size_t)bz * CC * NN;  B = Bin;
        M = NN; Nc = CC; K = CC; lda = NN; ldb = CC;
    } else if (MODE == 1) {    // rel
        A = d_pe; B = d_pe;
        M = NN; Nc = NN; K = CC; lda = CC; ldb = CC;
    } else if (MODE == 2) {    // dist candidates
        A = d_xn + (size_t)bz * NN * CC;  B = A;
        M = NN; Nc = NN; K = CC; lda = CC; ldb = CC;
    } else if (MODE == 3) {    // grouped conv
        int b = bz >> 2, g = bz & 3;
        A = d_gbuf + (size_t)b * NN * CC2 + g * CG;
        B = Bin + (size_t)g * CG * CG;
        M = NN; Nc = CG; K = CG; lda = CC2; ldb = CG;
    } else {                   // fc2
        A = d_ybuf; B = Bin;
        M = BB * NN; Nc = CC; K = CC2; lda = CC2; ldb = CC2;
    }

    __shared__ float As[2][16][128];
    __shared__ float Bs[2][16][128];

    const int tid = threadIdx.x;
    const int tx = tid & 15;
    const int ty = tid >> 4;
    const int m0 = blockIdx.y * 128;
    const int n0 = blockIdx.x * 128;

    // ---- load-pointer setup (branchless clamped)
    const float* aptr0;
    const float* aptr1;
    int a_st_k, a_st_m;        // smem store coords for MODE 0 path
    int a_st_r, a_st_kq;       // smem store coords for row-major path
    if (MODE == 0) {
        int k = tid >> 5;
        int m = (tid & 31) * 4;
        int mc = min(m0 + m, M - 4);
        aptr0 = A + (size_t)k * lda + mc;
        aptr1 = A + (size_t)(k + 8) * lda + mc;
        a_st_k = k; a_st_m = m;
        a_st_r = 0; a_st_kq = 0;
    } else {
        int r = tid >> 1;
        int kq = (tid & 1) * 8;
        int rc = min(m0 + r, M - 1);
        aptr0 = A + (size_t)rc * lda + kq;
        aptr1 = aptr0 + 4;
        a_st_r = r; a_st_kq = kq;
        a_st_k = 0; a_st_m = 0;
    }
    const int b_r  = tid >> 1;
    const int b_kq = (tid & 1) * 8;
    const float* bptr0 = B + (size_t)min(n0 + b_r, Nc - 1) * ldb + b_kq;
    const float* bptr1 = bptr0 + 4;

    float4 ra0, ra1, rb0, rb1;

    // ---- prologue
    ra0 = *reinterpret_cast<const float4*>(aptr0);
    ra1 = *reinterpret_cast<const float4*>(aptr1);
    rb0 = *reinterpret_cast<const float4*>(bptr0);
    rb1 = *reinterpret_cast<const float4*>(bptr1);
    if (MODE == 0) {
        *reinterpret_cast<float4*>(&As[0][a_st_k][a_st_m])     = ra0;
        *reinterpret_cast<float4*>(&As[0][a_st_k + 8][a_st_m]) = ra1;
    } else {
        As[0][a_st_kq + 0][a_st_r] = ra0.x; As[0][a_st_kq + 1][a_st_r] = ra0.y;
        As[0][a_st_kq + 2][a_st_r] = ra0.z; As[0][a_st_kq + 3][a_st_r] = ra0.w;
        As[0][a_st_kq + 4][a_st_r] = ra1.x; As[0][a_st_kq + 5][a_st_r] = ra1.y;
        As[0][a_st_kq + 6][a_st_r] = ra1.z; As[0][a_st_kq + 7][a_st_r] = ra1.w;
    }
    Bs[0][b_kq + 0][b_r] = rb0.x; Bs[0][b_kq + 1][b_r] = rb0.y;
    Bs[0][b_kq + 2][b_r] = rb0.z; Bs[0][b_kq + 3][b_r] = rb0.w;
    Bs[0][b_kq + 4][b_r] = rb1.x; Bs[0][b_kq + 5][b_r] = rb1.y;
    Bs[0][b_kq + 6][b_r] = rb1.z; Bs[0][b_kq + 7][b_r] = rb1.w;
    __syncthreads();

    float acc[8][8];
#pragma unroll
    for (int i = 0; i < 8; i++)
#pragma unroll
        for (int j = 0; j < 8; j++) acc[i][j] = 0.0f;

    const int T = K >> 4;
    for (int t = 0; t < T; t++) {
        const int cur = t & 1;
        if (t + 1 < T) {
            if (MODE == 0) { aptr0 += (size_t)16 * lda; aptr1 += (size_t)16 * lda; }
            else           { aptr0 += 16;               aptr1 += 16; }
            bptr0 += 16; bptr1 += 16;
            ra0 = *reinterpret_cast<const float4*>(aptr0);
            ra1 = *reinterpret_cast<const float4*>(aptr1);
            rb0 = *reinterpret_cast<const float4*>(bptr0);
            rb1 = *reinterpret_cast<const float4*>(bptr1);
        }
#pragma unroll
        for (int kk = 0; kk < 16; kk++) {
            float af[8], bf[8];
            *reinterpret_cast<float4*>(&af[0]) = *reinterpret_cast<const float4*>(&As[cur][kk][ty * 4]);
            *reinterpret_cast<float4*>(&af[4]) = *reinterpret_cast<const float4*>(&As[cur][kk][64 + ty * 4]);
            *reinterpret_cast<float4*>(&bf[0]) = *reinterpret_cast<const float4*>(&Bs[cur][kk][tx * 4]);
            *reinterpret_cast<float4*>(&bf[4]) = *reinterpret_cast<const float4*>(&Bs[cur][kk][64 + tx * 4]);
#pragma unroll
            for (int i = 0; i < 8; i++)
#pragma unroll
                for (int j = 0; j < 8; j++) acc[i][j] += af[i] * bf[j];
        }
        if (t + 1 < T) {
            const int nxt = cur ^ 1;
            if (MODE == 0) {
                *reinterpret_cast<float4*>(&As[nxt][a_st_k][a_st_m])     = ra0;
                *reinterpret_cast<float4*>(&As[nxt][a_st_k + 8][a_st_m]) = ra1;
            } else {
                As[nxt][a_st_kq + 0][a_st_r] = ra0.x; As[nxt][a_st_kq + 1][a_st_r] = ra0.y;
                As[nxt][a_st_kq + 2][a_st_r] = ra0.z; As[nxt][a_st_kq + 3][a_st_r] = ra0.w;
                As[nxt][a_st_kq + 4][a_st_r] = ra1.x; As[nxt][a_st_kq + 5][a_st_r] = ra1.y;
                As[nxt][a_st_kq + 6][a_st_r] = ra1.z; As[nxt][a_st_kq + 7][a_st_r] = ra1.w;
            }
            Bs[nxt][b_kq + 0][b_r] = rb0.x; Bs[nxt][b_kq + 1][b_r] = rb0.y;
            Bs[nxt][b_kq + 2][b_r] = rb0.z; Bs[nxt][b_kq + 3][b_r] = rb0.w;
            Bs[nxt][b_kq + 4][b_r] = rb1.x; Bs[nxt][b_kq + 5][b_r] = rb1.y;
            Bs[nxt][b_kq + 6][b_r] = rb1.z; Bs[nxt][b_kq + 7][b_r] = rb1.w;
        }
        __syncthreads();
    }

    int rows[8], cols[8], rows_l[8], cols_l[8];
#pragma unroll
    for (int i = 0; i < 4; i++) {
        rows_l[i]     = ty * 4 + i;
        rows_l[i + 4] = 64 + ty * 4 + i;
        cols_l[i]     = tx * 4 + i;
        cols_l[i + 4] = 64 + tx * 4 + i;
        rows[i] = m0 + rows_l[i];     rows[i + 4] = m0 + rows_l[i + 4];
        cols[i] = n0 + cols_l[i];     cols[i + 4] = n0 + cols_l[i + 4];
    }

    if (MODE == 1) {
        const float sc = -2.0f / (float)CC;
#pragma unroll
        for (int i = 0; i < 8; i++) {
            if (rows[i] >= M) continue;
            float* rr = d_rel + (size_t)rows[i] * NN;
#pragma unroll
            for (int j = 0; j < 8; j++)
                if (cols[j] < Nc) rr[cols[j]] = sc * acc[i][j];
        }
        // lower triangle of rel is never read -> no mirror write
    } else if (MODE == 2) {
        // ---- fused candidate top-9 generation (dist never materialized) ----
        float scol[8], srow[8];
#pragma unroll
        for (int j = 0; j < 8; j++)
            scol[j] = (cols[j] < NN) ? d_sq[bz * NN + cols[j]] : 0.0f;
#pragma unroll
        for (int i = 0; i < 8; i++)
            srow[i] = (rows[i] < NN) ? d_sq[bz * NN + rows[i]] : 0.0f;

        float* tileS = &As[0][0][0];          // [16][129] slab values
        float* cvS   = &As[0][0][0];          // overlays tile after scan
        int*   ciS   = (int*)&Bs[0][0][0];

        const int q = tid >> 4;               // 0..15 scan lane (8 cols each)
        const int r = tid & 15;               // 0..15 row within slab

        for (int orient = 0; orient < 2; orient++) {
            if (orient == 1 && blockIdx.x == blockIdx.y) break;
            const int ct      = (orient == 0) ? blockIdx.x : blockIdx.y;
            const int rowbase = (orient == 0) ? m0 : n0;
            const int colbase = (orient == 0) ? n0 : m0;

            for (int p = 0; p < 8; p++) {
                __syncthreads();    // prior pass emission done before overwrite
                // 1) init slab to +INF
                for (int z = tid; z < 16 * 129; z += 256) tileS[z] = INFINITY;
                __syncthreads();
                // 2) deposit dist values for this 16-row slab
                if (orient == 0) {
                    if ((ty >> 2) == (p & 3)) {
                        const int ih = (p < 4) ? 0 : 4;
#pragma unroll
                        for (int di = 0; di < 4; di++) {
                            int i = ih + di;
                            int lr = (ty & 3) * 4 + di;
                            if (rows[i] < NN) {
                                const float* rr = d_rel + (size_t)rows[i] * NN;
#pragma unroll
                                for (int j = 0; j < 8; j++)
                                    if (cols[j] < NN)
                                        tileS[lr * 129 + cols_l[j]] =
                                            scol[j] - 2.0f * acc[i][j] + rr[cols[j]];
                            }
                        }
                    }
                } else {
                    if ((tx >> 2) == (p & 3)) {
                        const int jh = (p < 4) ? 0 : 4;
#pragma unroll
                        for (int dj = 0; dj < 4; dj++) {
                            int j = jh + dj;
                            int lr = (tx & 3) * 4 + dj;
                            if (cols[j] < NN) {
#pragma unroll
                                for (int i = 0; i < 8; i++)
                                    if (rows[i] < NN)
                                        tileS[lr * 129 + rows_l[i]] =
                                            srow[i] - 2.0f * acc[i][j]
                                            + d_rel[(size_t)rows[i] * NN + cols[j]];
                            }
                        }
                    }
                }
                __syncthreads();
                // 3) per-thread top-9 over 8 columns of row r
                float tv[KNB]; int tix[KNB];
#pragma unroll
                for (int k = 0; k < KNB; k++) { tv[k] = INFINITY; tix[k] = 0x7fffffff; }
#pragma unroll
                for (int s = 0; s < 8; s++) {
                    int c = q * 8 + s;
                    float v = tileS[r * 129 + c];
                    int idx = colbase + c;
                    if (v < tv[KNB - 1] || (v == tv[KNB - 1] && idx < tix[KNB - 1])) {
                        tv[KNB - 1] = v; tix[KNB - 1] = idx;
#pragma unroll
                        for (int k = KNB - 1; k > 0; k--) {
                            bool sw = (tv[k] < tv[k - 1]) ||
                                      (tv[k] == tv[k - 1] && tix[k] < tix[k - 1]);
                            if (sw) {
                                float fv = tv[k]; tv[k] = tv[k - 1]; tv[k - 1] = fv;
                                int fi = tix[k]; tix[k] = tix[k - 1]; tix[k - 1] = fi;
                            }
                        }
                    }
                }
                __syncthreads();    // slab reads done; cv overlays slab
                // 4) stage sorted lists
#pragma unroll
                for (int k = 0; k < KNB; k++) {
                    cvS[(q * 16 + r) * KNB + k] = tv[k];
                    ciS[(q * 16 + r) * KNB + k] = tix[k];
                }
                // 5) log-tree merge of 16 lists per row
                for (int st = 8; st >= 1; st >>= 1) {
                    __syncthreads();
                    if (q < st) {
                        float* Av = &cvS[(q * 16 + r) * KNB];
                        int*   Ai = &ciS[(q * 16 + r) * KNB];
                        float* Bv = &cvS[((q + st) * 16 + r) * KNB];
                        int*   Bi = &ciS[((q + st) * 16 + r) * KNB];
                        float ov[KNB]; int oi[KNB];
                        int ia = 0, ib = 0;
#pragma unroll
                        for (int k = 0; k < KNB; k++) {
                            float va = Av[ia], vb = Bv[ib];
                            int xa = Ai[ia], xb = Bi[ib];
                            bool takeA = (va < vb) || (va == vb && xa < xb);
                            ov[k] = takeA ? va : vb;
                            oi[k] = takeA ? xa : xb;
                            if (takeA) ia++; else ib++;
                        }
#pragma unroll
                        for (int k = 0; k < KNB; k++) { Av[k] = ov[k]; Ai[k] = oi[k]; }
                    }
                }
                __syncthreads();
                // 6) emit 9 candidates per valid row  (layout [ct][b][row][9])
                if (q == 0) {
                    int rglob = rowbase + 16 * p + r;
                    if (rglob < NN) {
                        size_t off = ((size_t)ct * BB * NN + (size_t)bz * NN + rglob) * KNB;
#pragma unroll
                        for (int k = 0; k < KNB; k++) {
                            d_cv[off + k] = cvS[r * KNB + k];
                            d_ci[off + k] = ciS[r * KNB + k];
                        }
                    }
                }
            }
        }
    } else if (MODE == 0) {
        float sc[8], bi[8];
#pragma unroll
        for (int j = 0; j < 8; j++) {
            if (cols[j] < Nc) {
                float s = q1[cols[j]] * rsqrtf(q4[cols[j]] + BNEPS);
                sc[j] = s;
                bi[j] = (q0[cols[j]] - q3[cols[j]]) * s + q2[cols[j]];
            } else { sc[j] = 0.f; bi[j] = 0.f; }
        }
        float* hb = d_h + (size_t)bz * NN * CC;
#pragma unroll
        for (int i = 0; i < 8; i++) {
            if (rows[i] >= M) continue;
#pragma unroll
            for (int j = 0; j < 8; j++)
                if (cols[j] < Nc)
                    hb[(size_t)rows[i] * CC + cols[j]] = acc[i][j] * sc[j] + bi[j];
        }
    } else if (MODE == 3) {
        int b = bz >> 2, g = bz & 3;
        float sc[8], bi[8];
        int ch[8];
#pragma unroll
        for (int j = 0; j < 8; j++) {
            ch[j] = g * CG + cols[j];
            if (cols[j] < Nc) {
                float s = q1[ch[j]] * rsqrtf(q4[ch[j]] + BNEPS);
                sc[j] = s;
                bi[j] = (q0[ch[j]] - q3[ch[j]]) * s + q2[ch[j]];
            } else { sc[j] = 0.f; bi[j] = 0.f; }
        }
        float* yb = d_ybuf + (size_t)b * NN * CC2;
#pragma unroll
        for (int i = 0; i < 8; i++) {
            if (rows[i] >= M) continue;
#pragma unroll
            for (int j = 0; j < 8; j++)
                if (cols[j] < Nc) {
                    float t2 = acc[i][j] * sc[j] + bi[j];
                    yb[(size_t)rows[i] * CC2 + ch[j]] = t2 * normcdff(t2);  // exact GELU
                }
        }
    } else { // MODE 4
        float sc[8], bi[8];
#pragma unroll
        for (int j = 0; j < 8; j++) {
            if (cols[j] < Nc) {
                float s = q1[cols[j]] * rsqrtf(q4[cols[j]] + BNEPS);
                sc[j] = s;
                bi[j] = (q0[cols[j]] - q3[cols[j]]) * s + q2[cols[j]];
            } else { sc[j] = 0.f; bi[j] = 0.f; }
        }
#pragma unroll
        for (int i = 0; i < 8; i++) {
            if (rows[i] >= M) continue;
#pragma unroll
            for (int j = 0; j < 8; j++)
                if (cols[j] < Nc)
                    d_obuf[(size_t)rows[i] * CC + cols[j]] = acc[i][j] * sc[j] + bi[j];
        }
    }
}

// ---------------- row-wise L2 normalize + sq --------------------------------
__global__ void norm_kernel() {
    int row = blockIdx.x;                   // 0 .. B*N-1
    const float* hr = d_h + (size_t)row * CC;
    float* xr = d_xn + (size_t)row * CC;
    int t = threadIdx.x;                    // 64 threads
    float a0 = hr[t], a1 = hr[t + 64], a2 = hr[t + 128];
    float ss = a0 * a0 + a1 * a1 + a2 * a2;
#pragma unroll
    for (int o = 16; o > 0; o >>= 1) ss += __shfl_down_sync(0xffffffffu, ss, o);
    __shared__ float w1[2], w2[2];
    if ((t & 31) == 0) w1[t >> 5] = ss;
    __syncthreads();
    float norm = sqrtf(w1[0] + w1[1]);
    float inv = 1.0f / fmaxf(norm, 1e-12f);
    float x0 = a0 * inv, x1 = a1 * inv, x2 = a2 * inv;
    xr[t] = x0; xr[t + 64] = x1; xr[t + 128] = x2;
    float s2 = x0 * x0 + x1 * x1 + x2 * x2;
#pragma unroll
    for (int o = 16; o > 0; o >>= 1) s2 += __shfl_down_sync(0xffffffffu, s2, o);
    if ((t & 31) == 0) w2[t >> 5] = s2;
    __syncthreads();
    if (t == 0) d_sq[row] = w2[0] + w2[1];
}

// ---------------- merge 25 sorted candidate lists per row -> top-9 ----------
__global__ void merge_topk_kernel() {
    int row = blockIdx.x * blockDim.x + threadIdx.x;   // b*N + n
    if (row >= BB * NN) return;
    float tv[KNB]; int ti[KNB];
#pragma unroll
    for (int k = 0; k < KNB; k++) { tv[k] = INFINITY; ti[k] = 0x7fffffff; }
#pragma unroll 1
    for (int t = 0; t < NT; t++) {
        const float* cv = d_cv + ((size_t)t * BB * NN + row) * KNB;
        const int*   ci = d_ci + ((size_t)t * BB * NN + row) * KNB;
#pragma unroll 1
        for (int k = 0; k < KNB; k++) {
            float v = cv[k]; int idx = ci[k];
            if (v < tv[KNB - 1] || (v == tv[KNB - 1] && idx < ti[KNB - 1])) {
                tv[KNB - 1] = v; ti[KNB - 1] = idx;
#pragma unroll
                for (int q = KNB - 1; q > 0; q--) {
                    bool sw = (tv[q] < tv[q - 1]) ||
                              (tv[q] == tv[q - 1] && ti[q] < ti[q - 1]);
                    if (sw) {
                        float fv = tv[q]; tv[q] = tv[q - 1]; tv[q - 1] = fv;
                        int fi = ti[q]; ti[q] = ti[q - 1]; ti[q - 1] = fi;
                    }
                }
            } else break;   // source list sorted -> rest can't enter
        }
    }
#pragma unroll
    for (int k = 0; k < KNB; k++) d_nn[row * KNB + k] = ti[k];
}

// ---------------- gather neighbors, max-edge, build g -----------------------
__global__ void gather_kernel() {
    const int row = blockIdx.x;             // b*N + n
    const int b = row / NN;
    __shared__ int nnidx[KNB];
    if (threadIdx.x < KNB) nnidx[threadIdx.x] = d_nn[row * KNB + threadIdx.x];
    __syncthreads();
    const int c = threadIdx.x;              // 192 threads
    const float* hb = d_h + (size_t)b * NN * CC;
    float hn = d_h[(size_t)row * CC + c];
    float mx = -INFINITY;
#pragma unroll
    for (int j = 0; j < KNB; j++)
        mx = fmaxf(mx, hb[(size_t)nnidx[j] * CC + c] - hn);
    d_gbuf[(size_t)row * CC2 + c]      = hn;
    d_gbuf[(size_t)row * CC2 + CC + c] = mx;
}

// ---------------- transpose (B,N,C)->(B,C,N) + residual ---------------------
__global__ void out_kernel(const float* __restrict__ x, float* __restrict__ out) {
    __shared__ float tile[32][33];
    const int b = blockIdx.z;
    const int n0 = blockIdx.x * 32, c0 = blockIdx.y * 32;
    const int tx = threadIdx.x, ty = threadIdx.y;
#pragma unroll
    for (int i = 0; i < 32; i += 8)
        tile[ty + i][tx] = d_obuf[((size_t)b * NN + n0 + ty + i) * CC + c0 + tx];
    __syncthreads();
#pragma unroll
    for (int i = 0; i < 32; i += 8) {
        int c = c0 + ty + i, n = n0 + tx;
        size_t o = ((size_t)b * CC + c) * NN + n;
        out[o] = tile[tx][ty + i] + x[o];
    }
}

// ---------------- launch ----------------------------------------------------
extern "C" void kernel_launch(void* const* d_in, const int* in_sizes, int n_in,
                              void* d_out, int out_size)
{
    (void)in_sizes; (void)n_in; (void)out_size;
    const float* x     = (const float*)d_in[0];
    const float* fc1_w = (const float*)d_in[1];
    const float* fc1_b = (const float*)d_in[2];
    const float* bn1_g = (const float*)d_in[3];
    const float* bn1_b = (const float*)d_in[4];
    const float* bn1_m = (const float*)d_in[5];
    const float* bn1_v = (const float*)d_in[6];
    const float* gc_w  = (const float*)d_in[7];
    const float* gc_b  = (const float*)d_in[8];
    const float* bng_g = (const float*)d_in[9];
    const float* bng_b = (const float*)d_in[10];
    const float* bng_m = (const float*)d_in[11];
    const float* bng_v = (const float*)d_in[12];
    const float* fc2_w = (const float*)d_in[13];
    const float* fc2_b = (const float*)d_in[14];
    const float* bn2_g = (const float*)d_in[15];
    const float* bn2_b = (const float*)d_in[16];
    const float* bn2_m = (const float*)d_in[17];
    const float* bn2_v = (const float*)d_in[18];
    float* out = (float*)d_out;

    // pe + rel (batch-shared, upper-tri tiles only)
    pe_kernel<<<(NN * CC + 255) / 256, 256>>>();
    gemm_kernel<1><<<dim3(25, 25, 1), 256>>>(nullptr, nullptr, nullptr, nullptr, nullptr, nullptr, nullptr);

    // fc1 + bn1 -> h
    gemm_kernel<0><<<dim3(2, 25, BB), 256>>>(x, fc1_w, fc1_b, bn1_g, bn1_b, bn1_m, bn1_v);

    // normalize rows -> xn, sq
    norm_kernel<<<BB * NN, 64>>>();

    // dist GEMM with fused per-tile top-9 candidate generation
    gemm_kernel<2><<<dim3(25, 25, BB), 256>>>(nullptr, nullptr, nullptr, nullptr, nullptr, nullptr, nullptr);

    // merge candidate lists -> nn indices
    merge_topk_kernel<<<(BB * NN + 255) / 256, 256>>>();

    // gather + max-edge -> g = [h, d]
    gather_kernel<<<BB * NN, CC>>>();

    // grouped conv + bn + gelu -> y
    gemm_kernel<3><<<dim3(1, 25, BB * 4), 256>>>(nullptr, gc_w, gc_b, bng_g, bng_b, bng_m, bng_v);

    // fc2 + bn2 -> o
    gemm_kernel<4><<<dim3(2, 196, 1), 256>>>(nullptr, fc2_w, fc2_b, bn2_g, bn2_b, bn2_m, bn2_v);

    // transpose + residual -> out
    out_kernel<<<dim3(98, 6, BB), dim3(32, 8)>>>(x, out);
}

// round 6
// speedup vs baseline: 1.6774x; 1.6774x over previous
#include <cuda_runtime.h>
#include <math.h>

// Problem constants (fixed shapes from setup_inputs)
#define BB  8
#define CC  192
#define HH  56
#define WW  56
#define NN  3136            // H*W
#define CC2 384             // 2*C
#define CG  96              // C2/4
#define KNB 9               // K_NEIGHBORS
#define BNEPS 1e-5f

// ---------------- scratch (static device globals; no runtime alloc) --------
__device__ float d_pe  [NN * CC];                         //  2.4 MB
__device__ float d_rel [(size_t)NN * NN + 64];            // 39.3 MB (+pad)
__device__ float d_h   [(size_t)BB * NN * CC];            // 19.3 MB
__device__ float d_xn  [(size_t)BB * NN * CC];            // 19.3 MB
__device__ float d_sq  [BB * NN];
__device__ float d_dist[(size_t)BB * NN * NN];            // 314.7 MB
__device__ int   d_nn  [BB * NN * KNB];
__device__ float d_gbuf[(size_t)BB * NN * CC2];           // 38.6 MB
__device__ float d_ybuf[(size_t)BB * NN * CC2];           // 38.6 MB
__device__ float d_obuf[(size_t)BB * NN * CC];            // 19.3 MB

// ---------------- positional embedding -------------------------------------
__global__ void pe_kernel() {
    int i = blockIdx.x * blockDim.x + threadIdx.x;
    if (i >= NN * CC) return;
    int n = i / CC, k = i % CC;
    int yy = n / WW, xx = n % WW;
    float pos = (k < 96) ? (float)yy : (float)xx;
    int kk = k % 96;                       // within emb_h or emb_w
    int oi = (kk < 48) ? kk : kk - 48;     // omega index
    float omega = expf(-logf(10000.0f) * (float)oi / 48.0f);
    float ang = pos * omega;
    d_pe[i] = (kk < 48) ? sinf(ang) : cosf(ang);
}

// ---------------- 128x128x16 double-buffered SGEMM with mode epilogues ------
// C(m,n) = sum_k A(m,k) * B(n,k)
// MODE 0: fc1   A = x_b (stored KxM, "A-transposed"), epilogue bias+BN1 -> d_h
// MODE 1: rel   A=B=d_pe, SYMMETRIC: upper-tri tiles only, mirror write
// MODE 2: dist  A=B=d_xn_b, SYMMETRIC: upper-tri tiles only, both dist tiles
// MODE 3: group A = d_gbuf slice, B = gc_w[g], bias+BN+GELU -> d_ybuf
// MODE 4: fc2   A = d_ybuf (all batches), bias+BN2 -> d_obuf
template <int MODE>
__global__ void __launch_bounds__(256, 2)
gemm_kernel(const float* __restrict__ Ain, const float* __restrict__ Bin,
            const float* __restrict__ q0, const float* __restrict__ q1,
            const float* __restrict__ q2, const float* __restrict__ q3,
            const float* __restrict__ q4)
{
    // symmetric modes: only upper-triangle tiles (ti <= tj)
    if ((MODE == 1 || MODE == 2) && blockIdx.y > blockIdx.x) return;

    int M, Nc, K, lda, ldb;
    const float* A;
    const float* B;
    const int bz = blockIdx.z;

    if (MODE == 0) {           // fc1 (A stored K x M)
        A = Ain + (size_t)bz * CC * NN;  B = Bin;
        M = NN; Nc = CC; K = CC; lda = NN; ldb = CC;
    } else if (MODE == 1) {    // rel
        A = d_pe; B = d_pe;
        M = NN; Nc = NN; K = CC; lda = CC; ldb = CC;
    } else if (MODE == 2) {    // dist
        A = d_xn + (size_t)bz * NN * CC;  B = A;
        M = NN; Nc = NN; K = CC; lda = CC; ldb = CC;
    } else if (MODE == 3) {    // grouped conv
        int b = bz >> 2, g = bz & 3;
        A = d_gbuf + (size_t)b * NN * CC2 + g * CG;
        B = Bin + (size_t)g * CG * CG;
        M = NN; Nc = CG; K = CG; lda = CC2; ldb = CG;
    } else {                   // fc2
        A = d_ybuf; B = Bin;
        M = BB * NN; Nc = CC; K = CC2; lda = CC2; ldb = CC2;
    }

    __shared__ float As[2][16][128];
    __shared__ float Bs[2][16][128];

    const int tid = threadIdx.x;
    const int tx = tid & 15;
    const int ty = tid >> 4;
    const int m0 = blockIdx.y * 128;
    const int n0 = blockIdx.x * 128;

    // ---- load-pointer setup (branchless clamped; OOB rows duplicate, discarded in epilogue)
    const float* aptr0;
    const float* aptr1;
    int a_st_k, a_st_m;        // smem store coords for MODE 0 path
    int a_st_r, a_st_kq;       // smem store coords for row-major path
    if (MODE == 0) {
        int k = tid >> 5;                  // 0..7
        int m = (tid & 31) * 4;            // 0..124
        int mc = min(m0 + m, M - 4);
        aptr0 = A + (size_t)k * lda + mc;
        aptr1 = A + (size_t)(k + 8) * lda + mc;
        a_st_k = k; a_st_m = m;
        a_st_r = 0; a_st_kq = 0;
    } else {
        int r = tid >> 1;                  // 0..127
        int kq = (tid & 1) * 8;            // 0 or 8
        int rc = min(m0 + r, M - 1);
        aptr0 = A + (size_t)rc * lda + kq;
        aptr1 = aptr0 + 4;
        a_st_r = r; a_st_kq = kq;
        a_st_k = 0; a_st_m = 0;
    }
    const int b_r  = tid >> 1;
    const int b_kq = (tid & 1) * 8;
    const float* bptr0 = B + (size_t)min(n0 + b_r, Nc - 1) * ldb + b_kq;
    const float* bptr1 = bptr0 + 4;

    float4 ra0, ra1, rb0, rb1;

    // ---- prologue: load tile 0
    ra0 = *reinterpret_cast<const float4*>(aptr0);
    ra1 = *reinterpret_cast<const float4*>(aptr1);
    rb0 = *reinterpret_cast<const float4*>(bptr0);
    rb1 = *reinterpret_cast<const float4*>(bptr1);
    if (MODE == 0) {
        *reinterpret_cast<float4*>(&As[0][a_st_k][a_st_m])     = ra0;
        *reinterpret_cast<float4*>(&As[0][a_st_k + 8][a_st_m]) = ra1;
    } else {
        As[0][a_st_kq + 0][a_st_r] = ra0.x; As[0][a_st_kq + 1][a_st_r] = ra0.y;
        As[0][a_st_kq + 2][a_st_r] = ra0.z; As[0][a_st_kq + 3][a_st_r] = ra0.w;
        As[0][a_st_kq + 4][a_st_r] = ra1.x; As[0][a_st_kq + 5][a_st_r] = ra1.y;
        As[0][a_st_kq + 6][a_st_r] = ra1.z; As[0][a_st_kq + 7][a_st_r] = ra1.w;
    }
    Bs[0][b_kq + 0][b_r] = rb0.x; Bs[0][b_kq + 1][b_r] = rb0.y;
    Bs[0][b_kq + 2][b_r] = rb0.z; Bs[0][b_kq + 3][b_r] = rb0.w;
    Bs[0][b_kq + 4][b_r] = rb1.x; Bs[0][b_kq + 5][b_r] = rb1.y;
    Bs[0][b_kq + 6][b_r] = rb1.z; Bs[0][b_kq + 7][b_r] = rb1.w;
    __syncthreads();

    float acc[8][8];
#pragma unroll
    for (int i = 0; i < 8; i++)
#pragma unroll
        for (int j = 0; j < 8; j++) acc[i][j] = 0.0f;

    const int T = K >> 4;                  // number of 16-deep K slabs
    for (int t = 0; t < T; t++) {
        const int cur = t & 1;
        // prefetch next slab into registers
        if (t + 1 < T) {
            if (MODE == 0) { aptr0 += (size_t)16 * lda; aptr1 += (size_t)16 * lda; }
            else           { aptr0 += 16;               aptr1 += 16; }
            bptr0 += 16; bptr1 += 16;
            ra0 = *reinterpret_cast<const float4*>(aptr0);
            ra1 = *reinterpret_cast<const float4*>(aptr1);
            rb0 = *reinterpret_cast<const float4*>(bptr0);
            rb1 = *reinterpret_cast<const float4*>(bptr1);
        }
        // compute current slab
#pragma unroll
        for (int kk = 0; kk < 16; kk++) {
            float af[8], bf[8];
            *reinterpret_cast<float4*>(&af[0]) = *reinterpret_cast<const float4*>(&As[cur][kk][ty * 4]);
            *reinterpret_cast<float4*>(&af[4]) = *reinterpret_cast<const float4*>(&As[cur][kk][64 + ty * 4]);
            *reinterpret_cast<float4*>(&bf[0]) = *reinterpret_cast<const float4*>(&Bs[cur][kk][tx * 4]);
            *reinterpret_cast<float4*>(&bf[4]) = *reinterpret_cast<const float4*>(&Bs[cur][kk][64 + tx * 4]);
#pragma unroll
            for (int i = 0; i < 8; i++)
#pragma unroll
                for (int j = 0; j < 8; j++) acc[i][j] += af[i] * bf[j];
        }
        // stage next slab into the other smem buffer
        if (t + 1 < T) {
            const int nxt = cur ^ 1;
            if (MODE == 0) {
                *reinterpret_cast<float4*>(&As[nxt][a_st_k][a_st_m])     = ra0;
                *reinterpret_cast<float4*>(&As[nxt][a_st_k + 8][a_st_m]) = ra1;
            } else {
                As[nxt][a_st_kq + 0][a_st_r] = ra0.x; As[nxt][a_st_kq + 1][a_st_r] = ra0.y;
                As[nxt][a_st_kq + 2][a_st_r] = ra0.z; As[nxt][a_st_kq + 3][a_st_r] = ra0.w;
                As[nxt][a_st_kq + 4][a_st_r] = ra1.x; As[nxt][a_st_kq + 5][a_st_r] = ra1.y;
                As[nxt][a_st_kq + 6][a_st_r] = ra1.z; As[nxt][a_st_kq + 7][a_st_r] = ra1.w;
            }
            Bs[nxt][b_kq + 0][b_r] = rb0.x; Bs[nxt][b_kq + 1][b_r] = rb0.y;
            Bs[nxt][b_kq + 2][b_r] = rb0.z; Bs[nxt][b_kq + 3][b_r] = rb0.w;
            Bs[nxt][b_kq + 4][b_r] = rb1.x; Bs[nxt][b_kq + 5][b_r] = rb1.y;
            Bs[nxt][b_kq + 6][b_r] = rb1.z; Bs[nxt][b_kq + 7][b_r] = rb1.w;
        }
        __syncthreads();
    }

    int rows[8], cols[8];
#pragma unroll
    for (int i = 0; i < 4; i++) {
        rows[i]     = m0 + ty * 4 + i;
        rows[i + 4] = m0 + 64 + ty * 4 + i;
        cols[i]     = n0 + tx * 4 + i;
        cols[i + 4] = n0 + 64 + tx * 4 + i;
    }

    if (MODE == 1) {
        const float sc = -2.0f / (float)CC;
        // normal tile (guarded)
#pragma unroll
        for (int i = 0; i < 8; i++) {
            if (rows[i] >= M) continue;
            float* rr = d_rel + (size_t)rows[i] * NN;
#pragma unroll
            for (int j = 0; j < 8; j++)
                if (cols[j] < Nc) rr[cols[j]] = sc * acc[i][j];
        }
        // mirrored tile (rel symmetric); float4 fast path when 4-row group in bounds
        if (blockIdx.y != blockIdx.x) {
            const bool full0 = (rows[3] < M);
            const bool full1 = (rows[7] < M);
#pragma unroll
            for (int j = 0; j < 8; j++) {
                int m = cols[j];
                if (m >= Nc) continue;
                float* base = &d_rel[(size_t)m * NN];
                if (full0) {
                    float4 v;
                    v.x = sc * acc[0][j]; v.y = sc * acc[1][j];
                    v.z = sc * acc[2][j]; v.w = sc * acc[3][j];
                    *reinterpret_cast<float4*>(&base[rows[0]]) = v;
                } else {
#pragma unroll
                    for (int i = 0; i < 4; i++)
                        if (rows[i] < M) base[rows[i]] = sc * acc[i][j];
                }
                if (full1) {
                    float4 v;
                    v.x = sc * acc[4][j]; v.y = sc * acc[5][j];
                    v.z = sc * acc[6][j]; v.w = sc * acc[7][j];
                    *reinterpret_cast<float4*>(&base[rows[4]]) = v;
                } else {
#pragma unroll
                    for (int i = 4; i < 8; i++)
                        if (rows[i] < M) base[rows[i]] = sc * acc[i][j];
                }
            }
        }
    } else if (MODE == 2) {
        float scol[8], srow[8];
#pragma unroll
        for (int j = 0; j < 8; j++)
            scol[j] = (cols[j] < Nc) ? d_sq[bz * NN + cols[j]] : 0.0f;
#pragma unroll
        for (int i = 0; i < 8; i++)
            srow[i] = (rows[i] < M) ? d_sq[bz * NN + rows[i]] : 0.0f;
        float* db = d_dist + (size_t)bz * NN * NN;
        // normal tile: dist[n][m] = sq[m] - 2*dot + rel[n][m]   (guarded)
#pragma unroll
        for (int i = 0; i < 8; i++) {
            if (rows[i] >= M) continue;
            const float* rr = d_rel + (size_t)rows[i] * NN;
            float* dd = db + (size_t)rows[i] * NN;
#pragma unroll
            for (int j = 0; j < 8; j++)
                if (cols[j] < Nc)
                    dd[cols[j]] = scol[j] - 2.0f * acc[i][j] + rr[cols[j]];
        }
        // mirrored tile: dist[m][n] = sq[n] - 2*dot + rel[n][m]  (rel symmetric)
        if (blockIdx.y != blockIdx.x) {
            const bool full0 = (rows[3] < M);
            const bool full1 = (rows[7] < M);
#pragma unroll
            for (int j = 0; j < 8; j++) {
                int m = cols[j];
                if (m >= Nc) continue;
                float* base = &db[(size_t)m * NN];
                if (full0) {
                    float4 v;
                    v.x = srow[0] - 2.0f * acc[0][j] + d_rel[(size_t)rows[0] * NN + m];
                    v.y = srow[1] - 2.0f * acc[1][j] + d_rel[(size_t)rows[1] * NN + m];
                    v.z = srow[2] - 2.0f * acc[2][j] + d_rel[(size_t)rows[2] * NN + m];
                    v.w = srow[3] - 2.0f * acc[3][j] + d_rel[(size_t)rows[3] * NN + m];
                    *reinterpret_cast<float4*>(&base[rows[0]]) = v;
                } else {
#pragma unroll
                    for (int i = 0; i < 4; i++)
                        if (rows[i] < M)
                            base[rows[i]] = srow[i] - 2.0f * acc[i][j] + d_rel[(size_t)rows[i] * NN + m];
                }
                if (full1) {
                    float4 v;
                    v.x = srow[4] - 2.0f * acc[4][j] + d_rel[(size_t)rows[4] * NN + m];
                    v.y = srow[5] - 2.0f * acc[5][j] + d_rel[(size_t)rows[5] * NN + m];
                    v.z = srow[6] - 2.0f * acc[6][j] + d_rel[(size_t)rows[6] * NN + m];
                    v.w = srow[7] - 2.0f * acc[7][j] + d_rel[(size_t)rows[7] * NN + m];
                    *reinterpret_cast<float4*>(&base[rows[4]]) = v;
                } else {
#pragma unroll
                    for (int i = 4; i < 8; i++)
                        if (rows[i] < M)
                            base[rows[i]] = srow[i] - 2.0f * acc[i][j] + d_rel[(size_t)rows[i] * NN + m];
                }
            }
        }
    } else if (MODE == 0) {
        float sc[8], bi[8];
#pragma unroll
        for (int j = 0; j < 8; j++) {
            if (cols[j] < Nc) {
                float s = q1[cols[j]] * rsqrtf(q4[cols[j]] + BNEPS);
                sc[j] = s;
                bi[j] = (q0[cols[j]] - q3[cols[j]]) * s + q2[cols[j]];
            } else { sc[j] = 0.f; bi[j] = 0.f; }
        }
        float* hb = d_h + (size_t)bz * NN * CC;
#pragma unroll
        for (int i = 0; i < 8; i++) {
            if (rows[i] >= M) continue;
#pragma unroll
            for (int j = 0; j < 8; j++)
                if (cols[j] < Nc)
                    hb[(size_t)rows[i] * CC + cols[j]] = acc[i][j] * sc[j] + bi[j];
        }
    } else if (MODE == 3) {
        int b = bz >> 2, g = bz & 3;
        float sc[8], bi[8];
        int ch[8];
#pragma unroll
        for (int j = 0; j < 8; j++) {
            ch[j] = g * CG + cols[j];
            if (cols[j] < Nc) {
                float s = q1[ch[j]] * rsqrtf(q4[ch[j]] + BNEPS);
                sc[j] = s;
                bi[j] = (q0[ch[j]] - q3[ch[j]]) * s + q2[ch[j]];
            } else { sc[j] = 0.f; bi[j] = 0.f; }
        }
        float* yb = d_ybuf + (size_t)b * NN * CC2;
#pragma unroll
        for (int i = 0; i < 8; i++) {
            if (rows[i] >= M) continue;
#pragma unroll
            for (int j = 0; j < 8; j++)
                if (cols[j] < Nc) {
                    float t2 = acc[i][j] * sc[j] + bi[j];
                    yb[(size_t)rows[i] * CC2 + ch[j]] = t2 * normcdff(t2);  // exact GELU
                }
        }
    } else { // MODE 4
        float sc[8], bi[8];
#pragma unroll
        for (int j = 0; j < 8; j++) {
            if (cols[j] < Nc) {
                float s = q1[cols[j]] * rsqrtf(q4[cols[j]] + BNEPS);
                sc[j] = s;
                bi[j] = (q0[cols[j]] - q3[cols[j]]) * s + q2[cols[j]];
            } else { sc[j] = 0.f; bi[j] = 0.f; }
        }
#pragma unroll
        for (int i = 0; i < 8; i++) {
            if (rows[i] >= M) continue;
#pragma unroll
            for (int j = 0; j < 8; j++)
                if (cols[j] < Nc)
                    d_obuf[(size_t)rows[i] * CC + cols[j]] = acc[i][j] * sc[j] + bi[j];
        }
    }
}

// ---------------- row-wise L2 normalize + sq --------------------------------
__global__ void norm_kernel() {
    int row = blockIdx.x;                   // 0 .. B*N-1
    const float* hr = d_h + (size_t)row * CC;
    float* xr = d_xn + (size_t)row * CC;
    int t = threadIdx.x;                    // 64 threads
    float a0 = hr[t], a1 = hr[t + 64], a2 = hr[t + 128];
    float ss = a0 * a0 + a1 * a1 + a2 * a2;
#pragma unroll
    for (int o = 16; o > 0; o >>= 1) ss += __shfl_down_sync(0xffffffffu, ss, o);
    __shared__ float w1[2], w2[2];
    if ((t & 31) == 0) w1[t >> 5] = ss;
    __syncthreads();
    float norm = sqrtf(w1[0] + w1[1]);
    float inv = 1.0f / fmaxf(norm, 1e-12f);
    float x0 = a0 * inv, x1 = a1 * inv, x2 = a2 * inv;
    xr[t] = x0; xr[t + 64] = x1; xr[t + 128] = x2;
    float s2 = x0 * x0 + x1 * x1 + x2 * x2;
#pragma unroll
    for (int o = 16; o > 0; o >>= 1) s2 += __shfl_down_sync(0xffffffffu, s2, o);
    if ((t & 31) == 0) w2[t >> 5] = s2;
    __syncthreads();
    if (t == 0) d_sq[row] = w2[0] + w2[1];
}

// ---------------- top-9 smallest per dist row (float4 scan) ------------------
__global__ void __launch_bounds__(256) topk_kernel() {
    const int row = blockIdx.x;             // b*N + n
    const int b = row / NN, n = row % NN;
    const float4* dr4 = reinterpret_cast<const float4*>(
        d_dist + (size_t)b * NN * NN + (size_t)n * NN);

    float tv[KNB];
    int   ti[KNB];
#pragma unroll
    for (int q = 0; q < KNB; q++) { tv[q] = INFINITY; ti[q] = 0x7fffffff; }

    for (int i4 = threadIdx.x; i4 < NN / 4; i4 += 256) {
        float4 v4 = dr4[i4];
        const int mb = i4 * 4;
        float vv[4] = { v4.x, v4.y, v4.z, v4.w };
#pragma unroll
        for (int c = 0; c < 4; c++) {
            float v = vv[c];
            if (v < tv[KNB - 1]) {          // strict: ties keep earlier index
                tv[KNB - 1] = v; ti[KNB - 1] = mb + c;
#pragma unroll
                for (int q = KNB - 1; q > 0; q--) {
                    if (tv[q] < tv[q - 1]) {
                        float fv = tv[q]; tv[q] = tv[q - 1]; tv[q - 1] = fv;
                        int   fi = ti[q]; ti[q] = ti[q - 1]; ti[q - 1] = fi;
                    }
                }
            }
        }
    }

    __shared__ float sv[256 * KNB];
    __shared__ int   si[256 * KNB];
#pragma unroll
    for (int q = 0; q < KNB; q++) { sv[threadIdx.x * KNB + q] = tv[q]; si[threadIdx.x * KNB + q] = ti[q]; }

    for (int stride = 128; stride >= 1; stride >>= 1) {
        __syncthreads();
        if (threadIdx.x < (unsigned)stride) {
            float* Av = &sv[threadIdx.x * KNB];
            int*   Ai = &si[threadIdx.x * KNB];
            float* Bv = &sv[(threadIdx.x + stride) * KNB];
            int*   Bi = &si[(threadIdx.x + stride) * KNB];
            float ov[KNB]; int oi[KNB];
            int ia = 0, ib = 0;
#pragma unroll
            for (int q = 0; q < KNB; q++) {
                float va = (ia < KNB) ? Av[ia] : INFINITY;
                float vb = (ib < KNB) ? Bv[ib] : INFINITY;
                int xa = (ia < KNB) ? Ai[ia] : 0x7fffffff;
                int xb = (ib < KNB) ? Bi[ib] : 0x7fffffff;
                bool takeA = (va < vb) || (va == vb && xa < xb);
                ov[q] = takeA ? va : vb;
                oi[q] = takeA ? xa : xb;
                if (takeA) ia++; else ib++;
            }
#pragma unroll
            for (int q = 0; q < KNB; q++) { Av[q] = ov[q]; Ai[q] = oi[q]; }
        }
    }
    __syncthreads();
    if (threadIdx.x < KNB) d_nn[row * KNB + threadIdx.x] = si[threadIdx.x];
}

// ---------------- gather neighbors, max-edge, build g -----------------------
__global__ void gather_kernel() {
    const int row = blockIdx.x;             // b*N + n
    const int b = row / NN;
    __shared__ int nnidx[KNB];
    if (threadIdx.x < KNB) nnidx[threadIdx.x] = d_nn[row * KNB + threadIdx.x];
    __syncthreads();
    const int c = threadIdx.x;              // 192 threads
    const float* hb = d_h + (size_t)b * NN * CC;
    float hn = d_h[(size_t)row * CC + c];
    float mx = -INFINITY;
#pragma unroll
    for (int j = 0; j < KNB; j++)
        mx = fmaxf(mx, hb[(size_t)nnidx[j] * CC + c] - hn);
    d_gbuf[(size_t)row * CC2 + c]      = hn;
    d_gbuf[(size_t)row * CC2 + CC + c] = mx;
}

// ---------------- transpose (B,N,C)->(B,C,N) + residual ---------------------
__global__ void out_kernel(const float* __restrict__ x, float* __restrict__ out) {
    __shared__ float tile[32][33];
    const int b = blockIdx.z;
    const int n0 = blockIdx.x * 32, c0 = blockIdx.y * 32;
    const int tx = threadIdx.x, ty = threadIdx.y;
#pragma unroll
    for (int i = 0; i < 32; i += 8)
        tile[ty + i][tx] = d_obuf[((size_t)b * NN + n0 + ty + i) * CC + c0 + tx];
    __syncthreads();
#pragma unroll
    for (int i = 0; i < 32; i += 8) {
        int c = c0 + ty + i, n = n0 + tx;
        size_t o = ((size_t)b * CC + c) * NN + n;
        out[o] = tile[tx][ty + i] + x[o];
    }
}

// ---------------- launch ----------------------------------------------------
extern "C" void kernel_launch(void* const* d_in, const int* in_sizes, int n_in,
                              void* d_out, int out_size)
{
    (void)in_sizes; (void)n_in; (void)out_size;
    const float* x     = (const float*)d_in[0];
    const float* fc1_w = (const float*)d_in[1];
    const float* fc1_b = (const float*)d_in[2];
    const float* bn1_g = (const float*)d_in[3];
    const float* bn1_b = (const float*)d_in[4];
    const float* bn1_m = (const float*)d_in[5];
    const float* bn1_v = (const float*)d_in[6];
    const float* gc_w  = (const float*)d_in[7];
    const float* gc_b  = (const float*)d_in[8];
    const float* bng_g = (const float*)d_in[9];
    const float* bng_b = (const float*)d_in[10];
    const float* bng_m = (const float*)d_in[11];
    const float* bng_v = (const float*)d_in[12];
    const float* fc2_w = (const float*)d_in[13];
    const float* fc2_b = (const float*)d_in[14];
    const float* bn2_g = (const float*)d_in[15];
    const float* bn2_b = (const float*)d_in[16];
    const float* bn2_m = (const float*)d_in[17];
    const float* bn2_v = (const float*)d_in[18];
    float* out = (float*)d_out;

    // pe + rel (batch-shared, symmetric: upper-tri tiles only)
    pe_kernel<<<(NN * CC + 255) / 256, 256>>>();
    gemm_kernel<1><<<dim3(25, 25, 1), 256>>>(nullptr, nullptr, nullptr, nullptr, nullptr, nullptr, nullptr);

    // fc1 + bn1 -> h
    gemm_kernel<0><<<dim3(2, 25, BB), 256>>>(x, fc1_w, fc1_b, bn1_g, bn1_b, bn1_m, bn1_v);

    // normalize rows -> xn, sq
    norm_kernel<<<BB * NN, 64>>>();

    // dist = sq[m] - 2 xn.xn^T + rel  (dominant GEMM, symmetric dot)
    gemm_kernel<2><<<dim3(25, 25, BB), 256>>>(nullptr, nullptr, nullptr, nullptr, nullptr, nullptr, nullptr);

    // per-row top-9 smallest -> nn indices
    topk_kernel<<<BB * NN, 256>>>();

    // gather + max-edge -> g = [h, d]
    gather_kernel<<<BB * NN, CC>>>();

    // grouped conv + bn + gelu -> y
    gemm_kernel<3><<<dim3(1, 25, BB * 4), 256>>>(nullptr, gc_w, gc_b, bng_g, bng_b, bng_m, bng_v);

    // fc2 + bn2 -> o
    gemm_kernel<4><<<dim3(2, 196, 1), 256>>>(nullptr, fc2_w, fc2_b, bn2_g, bn2_b, bn2_m, bn2_v);

    // transpose + residual -> out
    out_kernel<<<dim3(98, 6, BB), dim3(32, 8)>>>(x, out);
}

// round 7
// speedup vs baseline: 1.7272x; 1.0297x over previous
#include <cuda_runtime.h>
#include <math.h>

// Problem constants (fixed shapes from setup_inputs)
#define BB  8
#define CC  192
#define HH  56
#define WW  56
#define NN  3136            // H*W
#define CC2 384             // 2*C
#define CG  96              // C2/4
#define KNB 9               // K_NEIGHBORS
#define BNEPS 1e-5f

// ---------------- scratch (static device globals; no runtime alloc) --------
__device__ float d_peT [CC * NN];                         //  2.4 MB (K-major)
__device__ float d_rel [(size_t)NN * NN + 64];            // 39.3 MB (+pad)
__device__ float d_h   [(size_t)BB * NN * CC];            // 19.3 MB
__device__ float d_xn  [(size_t)BB * NN * CC];            // 19.3 MB (row-major)
__device__ float d_xnT [(size_t)BB * CC * NN];            // 19.3 MB (K-major)
__device__ float d_sq  [BB * NN];
__device__ float d_dist[(size_t)BB * NN * NN];            // 314.7 MB
__device__ float d_gbuf[(size_t)BB * NN * CC2];           // 38.6 MB
__device__ float d_ybuf[(size_t)BB * NN * CC2];           // 38.6 MB
__device__ float d_obuf[(size_t)BB * NN * CC];            // 19.3 MB

// ---------------- positional embedding (K-major write, coalesced) -----------
__global__ void pe_kernel() {
    int i = blockIdx.x * blockDim.x + threadIdx.x;
    if (i >= NN * CC) return;
    int k = i / NN, n = i % NN;
    int yy = n / WW, xx = n % WW;
    float pos = (k < 96) ? (float)yy : (float)xx;
    int kk = k % 96;                       // within emb_h or emb_w
    int oi = (kk < 48) ? kk : kk - 48;     // omega index
    float omega = expf(-logf(10000.0f) * (float)oi / 48.0f);
    float ang = pos * omega;
    d_peT[i] = (kk < 48) ? sinf(ang) : cosf(ang);
}

// ---------------- 128x128x16 double-buffered SGEMM with mode epilogues ------
// C(m,n) = sum_k A(m,k) * B(n,k)
// MODE 0: fc1   A = x_b (K-major), B = fc1_w row-major, bias+BN1 -> d_h
// MODE 1: rel   A=B=d_peT (K-major), SYMMETRIC upper-tri, mirror write
// MODE 2: dist  A=B=d_xnT_b (K-major), SYMMETRIC upper-tri, both dist tiles
// MODE 3: group A = d_gbuf slice row-major, B = gc_w[g], bias+BN+GELU -> d_ybuf
// MODE 4: fc2   A = d_ybuf row-major, bias+BN2 -> d_obuf
template <int MODE>
__global__ void __launch_bounds__(256, 2)
gemm_kernel(const float* __restrict__ Ain, const float* __restrict__ Bin,
            const float* __restrict__ q0, const float* __restrict__ q1,
            const float* __restrict__ q2, const float* __restrict__ q3,
            const float* __restrict__ q4)
{
    // symmetric modes: only upper-triangle tiles (ti <= tj)
    if ((MODE == 1 || MODE == 2) && blockIdx.y > blockIdx.x) return;

    constexpr bool AKM = (MODE <= 2);               // A stored K-major
    constexpr bool BKM = (MODE == 1 || MODE == 2);  // B stored K-major

    int M, Nc, K, lda, ldb;
    const float* A;
    const float* B;
    const int bz = blockIdx.z;

    if (MODE == 0) {           // fc1
        A = Ain + (size_t)bz * CC * NN;  B = Bin;
        M = NN; Nc = CC; K = CC; lda = NN; ldb = CC;
    } else if (MODE == 1) {    // rel
        A = d_peT; B = d_peT;
        M = NN; Nc = NN; K = CC; lda = NN; ldb = NN;
    } else if (MODE == 2) {    // dist
        A = d_xnT + (size_t)bz * CC * NN;  B = A;
        M = NN; Nc = NN; K = CC; lda = NN; ldb = NN;
    } else if (MODE == 3) {    // grouped conv
        int b = bz >> 2, g = bz & 3;
        A = d_gbuf + (size_t)b * NN * CC2 + g * CG;
        B = Bin + (size_t)g * CG * CG;
        M = NN; Nc = CG; K = CG; lda = CC2; ldb = CG;
    } else {                   // fc2
        A = d_ybuf; B = Bin;
        M = BB * NN; Nc = CC; K = CC2; lda = CC2; ldb = CC2;
    }

    __shared__ float As[2][16][128];
    __shared__ float Bs[2][16][128];

    const int tid = threadIdx.x;
    const int tx = tid & 15;
    const int ty = tid >> 4;
    const int m0 = blockIdx.y * 128;
    const int n0 = blockIdx.x * 128;

    // ---- A load-pointer setup
    const float* aptr0;
    const float* aptr1;
    int a_km_k = 0, a_km_m = 0;    // K-major coords
    int a_rm_r = 0, a_rm_kq = 0;   // row-major coords
    if (AKM) {
        a_km_k = tid >> 5;                 // 0..7
        a_km_m = (tid & 31) * 4;           // 0..124
        int mc = min(m0 + a_km_m, M - 4);
        aptr0 = A + (size_t)a_km_k * lda + mc;
        aptr1 = A + (size_t)(a_km_k + 8) * lda + mc;
    } else {
        a_rm_r  = tid >> 1;                // 0..127
        a_rm_kq = (tid & 1) * 8;           // 0 or 8
        int rc = min(m0 + a_rm_r, M - 1);
        aptr0 = A + (size_t)rc * lda + a_rm_kq;
        aptr1 = aptr0 + 4;
    }
    // ---- B load-pointer setup
    const float* bptr0;
    const float* bptr1;
    int b_km_k = 0, b_km_n = 0;
    int b_rm_r = 0, b_rm_kq = 0;
    if (BKM) {
        b_km_k = tid >> 5;
        b_km_n = (tid & 31) * 4;
        int nc = min(n0 + b_km_n, Nc - 4);
        bptr0 = B + (size_t)b_km_k * ldb + nc;
        bptr1 = B + (size_t)(b_km_k + 8) * ldb + nc;
    } else {
        b_rm_r  = tid >> 1;
        b_rm_kq = (tid & 1) * 8;
        int rc = min(n0 + b_rm_r, Nc - 1);
        bptr0 = B + (size_t)rc * ldb + b_rm_kq;
        bptr1 = bptr0 + 4;
    }

    float4 ra0, ra1, rb0, rb1;

    // ---- prologue: load tile 0
    ra0 = *reinterpret_cast<const float4*>(aptr0);
    ra1 = *reinterpret_cast<const float4*>(aptr1);
    rb0 = *reinterpret_cast<const float4*>(bptr0);
    rb1 = *reinterpret_cast<const float4*>(bptr1);
    if (AKM) {
        *reinterpret_cast<float4*>(&As[0][a_km_k][a_km_m])     = ra0;
        *reinterpret_cast<float4*>(&As[0][a_km_k + 8][a_km_m]) = ra1;
    } else {
        As[0][a_rm_kq + 0][a_rm_r] = ra0.x; As[0][a_rm_kq + 1][a_rm_r] = ra0.y;
        As[0][a_rm_kq + 2][a_rm_r] = ra0.z; As[0][a_rm_kq + 3][a_rm_r] = ra0.w;
        As[0][a_rm_kq + 4][a_rm_r] = ra1.x; As[0][a_rm_kq + 5][a_rm_r] = ra1.y;
        As[0][a_rm_kq + 6][a_rm_r] = ra1.z; As[0][a_rm_kq + 7][a_rm_r] = ra1.w;
    }
    if (BKM) {
        *reinterpret_cast<float4*>(&Bs[0][b_km_k][b_km_n])     = rb0;
        *reinterpret_cast<float4*>(&Bs[0][b_km_k + 8][b_km_n]) = rb1;
    } else {
        Bs[0][b_rm_kq + 0][b_rm_r] = rb0.x; Bs[0][b_rm_kq + 1][b_rm_r] = rb0.y;
        Bs[0][b_rm_kq + 2][b_rm_r] = rb0.z; Bs[0][b_rm_kq + 3][b_rm_r] = rb0.w;
        Bs[0][b_rm_kq + 4][b_rm_r] = rb1.x; Bs[0][b_rm_kq + 5][b_rm_r] = rb1.y;
        Bs[0][b_rm_kq + 6][b_rm_r] = rb1.z; Bs[0][b_rm_kq + 7][b_rm_r] = rb1.w;
    }
    __syncthreads();

    float acc[8][8];
#pragma unroll
    for (int i = 0; i < 8; i++)
#pragma unroll
        for (int j = 0; j < 8; j++) acc[i][j] = 0.0f;

    const int T = K >> 4;                  // number of 16-deep K slabs
    for (int t = 0; t < T; t++) {
        const int cur = t & 1;
        // prefetch next slab into registers
        if (t + 1 < T) {
            if (AKM) { aptr0 += (size_t)16 * lda; aptr1 += (size_t)16 * lda; }
            else     { aptr0 += 16;               aptr1 += 16; }
            if (BKM) { bptr0 += (size_t)16 * ldb; bptr1 += (size_t)16 * ldb; }
            else     { bptr0 += 16;               bptr1 += 16; }
            ra0 = *reinterpret_cast<const float4*>(aptr0);
            ra1 = *reinterpret_cast<const float4*>(aptr1);
            rb0 = *reinterpret_cast<const float4*>(bptr0);
            rb1 = *reinterpret_cast<const float4*>(bptr1);
        }
        // compute current slab
#pragma unroll
        for (int kk = 0; kk < 16; kk++) {
            float af[8], bf[8];
            *reinterpret_cast<float4*>(&af[0]) = *reinterpret_cast<const float4*>(&As[cur][kk][ty * 4]);
            *reinterpret_cast<float4*>(&af[4]) = *reinterpret_cast<const float4*>(&As[cur][kk][64 + ty * 4]);
            *reinterpret_cast<float4*>(&bf[0]) = *reinterpret_cast<const float4*>(&Bs[cur][kk][tx * 4]);
            *reinterpret_cast<float4*>(&bf[4]) = *reinterpret_cast<const float4*>(&Bs[cur][kk][64 + tx * 4]);
#pragma unroll
            for (int i = 0; i < 8; i++)
#pragma unroll
                for (int j = 0; j < 8; j++) acc[i][j] += af[i] * bf[j];
        }
        // stage next slab into the other smem buffer
        if (t + 1 < T) {
            const int nxt = cur ^ 1;
            if (AKM) {
                *reinterpret_cast<float4*>(&As[nxt][a_km_k][a_km_m])     = ra0;
                *reinterpret_cast<float4*>(&As[nxt][a_km_k + 8][a_km_m]) = ra1;
            } else {
                As[nxt][a_rm_kq + 0][a_rm_r] = ra0.x; As[nxt][a_rm_kq + 1][a_rm_r] = ra0.y;
                As[nxt][a_rm_kq + 2][a_rm_r] = ra0.z; As[nxt][a_rm_kq + 3][a_rm_r] = ra0.w;
                As[nxt][a_rm_kq + 4][a_rm_r] = ra1.x; As[nxt][a_rm_kq + 5][a_rm_r] = ra1.y;
                As[nxt][a_rm_kq + 6][a_rm_r] = ra1.z; As[nxt][a_rm_kq + 7][a_rm_r] = ra1.w;
            }
            if (BKM) {
                *reinterpret_cast<float4*>(&Bs[nxt][b_km_k][b_km_n])     = rb0;
                *reinterpret_cast<float4*>(&Bs[nxt][b_km_k + 8][b_km_n]) = rb1;
            } else {
                Bs[nxt][b_rm_kq + 0][b_rm_r] = rb0.x; Bs[nxt][b_rm_kq + 1][b_rm_r] = rb0.y;
                Bs[nxt][b_rm_kq + 2][b_rm_r] = rb0.z; Bs[nxt][b_rm_kq + 3][b_rm_r] = rb0.w;
                Bs[nxt][b_rm_kq + 4][b_rm_r] = rb1.x; Bs[nxt][b_rm_kq + 5][b_rm_r] = rb1.y;
                Bs[nxt][b_rm_kq + 6][b_rm_r] = rb1.z; Bs[nxt][b_rm_kq + 7][b_rm_r] = rb1.w;
            }
        }
        __syncthreads();
    }

    int rows[8], cols[8];
#pragma unroll
    for (int i = 0; i < 4; i++) {
        rows[i]     = m0 + ty * 4 + i;
        rows[i + 4] = m0 + 64 + ty * 4 + i;
        cols[i]     = n0 + tx * 4 + i;
        cols[i + 4] = n0 + 64 + tx * 4 + i;
    }

    if (MODE == 1) {
        const float sc = -2.0f / (float)CC;
        // normal tile (guarded)
#pragma unroll
        for (int i = 0; i < 8; i++) {
            if (rows[i] >= M) continue;
            float* rr = d_rel + (size_t)rows[i] * NN;
#pragma unroll
            for (int j = 0; j < 8; j++)
                if (cols[j] < Nc) rr[cols[j]] = sc * acc[i][j];
        }
        // mirrored tile (rel symmetric)
        if (blockIdx.y != blockIdx.x) {
            const bool full0 = (rows[3] < M);
            const bool full1 = (rows[7] < M);
#pragma unroll
            for (int j = 0; j < 8; j++) {
                int m = cols[j];
                if (m >= Nc) continue;
                float* base = &d_rel[(size_t)m * NN];
                if (full0) {
                    float4 v;
                    v.x = sc * acc[0][j]; v.y = sc * acc[1][j];
                    v.z = sc * acc[2][j]; v.w = sc * acc[3][j];
                    *reinterpret_cast<float4*>(&base[rows[0]]) = v;
                } else {
#pragma unroll
                    for (int i = 0; i < 4; i++)
                        if (rows[i] < M) base[rows[i]] = sc * acc[i][j];
                }
                if (full1) {
                    float4 v;
                    v.x = sc * acc[4][j]; v.y = sc * acc[5][j];
                    v.z = sc * acc[6][j]; v.w = sc * acc[7][j];
                    *reinterpret_cast<float4*>(&base[rows[4]]) = v;
                } else {
#pragma unroll
                    for (int i = 4; i < 8; i++)
                        if (rows[i] < M) base[rows[i]] = sc * acc[i][j];
                }
            }
        }
    } else if (MODE == 2) {
        float scol[8], srow[8];
#pragma unroll
        for (int j = 0; j < 8; j++)
            scol[j] = (cols[j] < Nc) ? d_sq[bz * NN + cols[j]] : 0.0f;
#pragma unroll
        for (int i = 0; i < 8; i++)
            srow[i] = (rows[i] < M) ? d_sq[bz * NN + rows[i]] : 0.0f;
        float* db = d_dist + (size_t)bz * NN * NN;
        // normal tile: dist[n][m] = sq[m] - 2*dot + rel[n][m]   (guarded)
#pragma unroll
        for (int i = 0; i < 8; i++) {
            if (rows[i] >= M) continue;
            const float* rr = d_rel + (size_t)rows[i] * NN;
            float* dd = db + (size_t)rows[i] * NN;
#pragma unroll
            for (int j = 0; j < 8; j++)
                if (cols[j] < Nc)
                    dd[cols[j]] = scol[j] - 2.0f * acc[i][j] + rr[cols[j]];
        }
        // mirrored tile: dist[m][n] = sq[n] - 2*dot + rel[n][m]  (rel symmetric)
        if (blockIdx.y != blockIdx.x) {
            const bool full0 = (rows[3] < M);
            const bool full1 = (rows[7] < M);
#pragma unroll
            for (int j = 0; j < 8; j++) {
                int m = cols[j];
                if (m >= Nc) continue;
                float* base = &db[(size_t)m * NN];
                if (full0) {
                    float4 v;
                    v.x = srow[0] - 2.0f * acc[0][j] + d_rel[(size_t)rows[0] * NN + m];
                    v.y = srow[1] - 2.0f * acc[1][j] + d_rel[(size_t)rows[1] * NN + m];
                    v.z = srow[2] - 2.0f * acc[2][j] + d_rel[(size_t)rows[2] * NN + m];
                    v.w = srow[3] - 2.0f * acc[3][j] + d_rel[(size_t)rows[3] * NN + m];
                    *reinterpret_cast<float4*>(&base[rows[0]]) = v;
                } else {
#pragma unroll
                    for (int i = 0; i < 4; i++)
                        if (rows[i] < M)
                            base[rows[i]] = srow[i] - 2.0f * acc[i][j] + d_rel[(size_t)rows[i] * NN + m];
                }
                if (full1) {
                    float4 v;
                    v.x = srow[4] - 2.0f * acc[4][j] + d_rel[(size_t)rows[4] * NN + m];
                    v.y = srow[5] - 2.0f * acc[5][j] + d_rel[(size_t)rows[5] * NN + m];
                    v.z = srow[6] - 2.0f * acc[6][j] + d_rel[(size_t)rows[6] * NN + m];
                    v.w = srow[7] - 2.0f * acc[7][j] + d_rel[(size_t)rows[7] * NN + m];
                    *reinterpret_cast<float4*>(&base[rows[4]]) = v;
                } else {
#pragma unroll
                    for (int i = 4; i < 8; i++)
                        if (rows[i] < M)
                            base[rows[i]] = srow[i] - 2.0f * acc[i][j] + d_rel[(size_t)rows[i] * NN + m];
                }
            }
        }
    } else if (MODE == 0) {
        float sc[8], bi[8];
#pragma unroll
        for (int j = 0; j < 8; j++) {
            if (cols[j] < Nc) {
                float s = q1[cols[j]] * rsqrtf(q4[cols[j]] + BNEPS);
                sc[j] = s;
                bi[j] = (q0[cols[j]] - q3[cols[j]]) * s + q2[cols[j]];
            } else { sc[j] = 0.f; bi[j] = 0.f; }
        }
        float* hb = d_h + (size_t)bz * NN * CC;
#pragma unroll
        for (int i = 0; i < 8; i++) {
            if (rows[i] >= M) continue;
#pragma unroll
            for (int j = 0; j < 8; j++)
                if (cols[j] < Nc)
                    hb[(size_t)rows[i] * CC + cols[j]] = acc[i][j] * sc[j] + bi[j];
        }
    } else if (MODE == 3) {
        int b = bz >> 2, g = bz & 3;
        float sc[8], bi[8];
        int ch[8];
#pragma unroll
        for (int j = 0; j < 8; j++) {
            ch[j] = g * CG + cols[j];
            if (cols[j] < Nc) {
                float s = q1[ch[j]] * rsqrtf(q4[ch[j]] + BNEPS);
                sc[j] = s;
                bi[j] = (q0[ch[j]] - q3[ch[j]]) * s + q2[ch[j]];
            } else { sc[j] = 0.f; bi[j] = 0.f; }
        }
        float* yb = d_ybuf + (size_t)b * NN * CC2;
#pragma unroll
        for (int i = 0; i < 8; i++) {
            if (rows[i] >= M) continue;
#pragma unroll
            for (int j = 0; j < 8; j++)
                if (cols[j] < Nc) {
                    float t2 = acc[i][j] * sc[j] + bi[j];
                    yb[(size_t)rows[i] * CC2 + ch[j]] = t2 * normcdff(t2);  // exact GELU
                }
        }
    } else { // MODE 4
        float sc[8], bi[8];
#pragma unroll
        for (int j = 0; j < 8; j++) {
            if (cols[j] < Nc) {
                float s = q1[cols[j]] * rsqrtf(q4[cols[j]] + BNEPS);
                sc[j] = s;
                bi[j] = (q0[cols[j]] - q3[cols[j]]) * s + q2[cols[j]];
            } else { sc[j] = 0.f; bi[j] = 0.f; }
        }
#pragma unroll
        for (int i = 0; i < 8; i++) {
            if (rows[i] >= M) continue;
#pragma unroll
            for (int j = 0; j < 8; j++)
                if (cols[j] < Nc)
                    d_obuf[(size_t)rows[i] * CC + cols[j]] = acc[i][j] * sc[j] + bi[j];
        }
    }
}

// ---------------- row-wise L2 normalize + sq --------------------------------
__global__ void norm_kernel() {
    int row = blockIdx.x;                   // 0 .. B*N-1
    const float* hr = d_h + (size_t)row * CC;
    float* xr = d_xn + (size_t)row * CC;
    int t = threadIdx.x;                    // 64 threads
    float a0 = hr[t], a1 = hr[t + 64], a2 = hr[t + 128];
    float ss = a0 * a0 + a1 * a1 + a2 * a2;
#pragma unroll
    for (int o = 16; o > 0; o >>= 1) ss += __shfl_down_sync(0xffffffffu, ss, o);
    __shared__ float w1[2], w2[2];
    if ((t & 31) == 0) w1[t >> 5] = ss;
    __syncthreads();
    float norm = sqrtf(w1[0] + w1[1]);
    float inv = 1.0f / fmaxf(norm, 1e-12f);
    float x0 = a0 * inv, x1 = a1 * inv, x2 = a2 * inv;
    xr[t] = x0; xr[t + 64] = x1; xr[t + 128] = x2;
    float s2 = x0 * x0 + x1 * x1 + x2 * x2;
#pragma unroll
    for (int o = 16; o > 0; o >>= 1) s2 += __shfl_down_sync(0xffffffffu, s2, o);
    if ((t & 31) == 0) w2[t >> 5] = s2;
    __syncthreads();
    if (t == 0) d_sq[row] = w2[0] + w2[1];
}

// ---------------- transpose xn (B,N,C) -> xnT (B,C,N) -----------------------
__global__ void xnt_kernel() {
    __shared__ float tile[32][33];
    const int b = blockIdx.z;
    const int n0 = blockIdx.x * 32, c0 = blockIdx.y * 32;
    const int tx = threadIdx.x, ty = threadIdx.y;
#pragma unroll
    for (int i = 0; i < 32; i += 8)
        tile[ty + i][tx] = d_xn[((size_t)b * NN + n0 + ty + i) * CC + c0 + tx];
    __syncthreads();
#pragma unroll
    for (int i = 0; i < 32; i += 8) {
        int c = c0 + ty + i, n = n0 + tx;
        d_xnT[((size_t)b * CC + c) * NN + n] = tile[tx][ty + i];
    }
}

// ---------------- fused top-9 + gather/max-edge ------------------------------
__global__ void __launch_bounds__(256) topk_gather_kernel() {
    const int row = blockIdx.x;             // b*N + n
    const int b = row / NN, n = row % NN;
    const float4* dr4 = reinterpret_cast<const float4*>(
        d_dist + (size_t)b * NN * NN + (size_t)n * NN);

    float tv[KNB];
    int   ti[KNB];
#pragma unroll
    for (int q = 0; q < KNB; q++) { tv[q] = INFINITY; ti[q] = 0x7fffffff; }

    for (int i4 = threadIdx.x; i4 < NN / 4; i4 += 256) {
        float4 v4 = dr4[i4];
        const int mb = i4 * 4;
        float vv[4] = { v4.x, v4.y, v4.z, v4.w };
#pragma unroll
        for (int c = 0; c < 4; c++) {
            float v = vv[c];
            if (v < tv[KNB - 1]) {          // strict: ties keep earlier index
                tv[KNB - 1] = v; ti[KNB - 1] = mb + c;
#pragma unroll
                for (int q = KNB - 1; q > 0; q--) {
                    if (tv[q] < tv[q - 1]) {
                        float fv = tv[q]; tv[q] = tv[q - 1]; tv[q - 1] = fv;
                        int   fi = ti[q]; ti[q] = ti[q - 1]; ti[q - 1] = fi;
                    }
                }
            }
        }
    }

    __shared__ float sv[256 * KNB];
    __shared__ int   si[256 * KNB];
#pragma unroll
    for (int q = 0; q < KNB; q++) { sv[threadIdx.x * KNB + q] = tv[q]; si[threadIdx.x * KNB + q] = ti[q]; }

    for (int stride = 128; stride >= 1; stride >>= 1) {
        __syncthreads();
        if (threadIdx.x < (unsigned)stride) {
            float* Av = &sv[threadIdx.x * KNB];
            int*   Ai = &si[threadIdx.x * KNB];
            float* Bv = &sv[(threadIdx.x + stride) * KNB];
            int*   Bi = &si[(threadIdx.x + stride) * KNB];
            float ov[KNB]; int oi[KNB];
            int ia = 0, ib = 0;
#pragma unroll
            for (int q = 0; q < KNB; q++) {
                float va = (ia < KNB) ? Av[ia] : INFINITY;
                float vb = (ib < KNB) ? Bv[ib] : INFINITY;
                int xa = (ia < KNB) ? Ai[ia] : 0x7fffffff;
                int xb = (ib < KNB) ? Bi[ib] : 0x7fffffff;
                bool takeA = (va < vb) || (va == vb && xa < xb);
                ov[q] = takeA ? va : vb;
                oi[q] = takeA ? xa : xb;
                if (takeA) ia++; else ib++;
            }
#pragma unroll
            for (int q = 0; q < KNB; q++) { Av[q] = ov[q]; Ai[q] = oi[q]; }
        }
    }
    __syncthreads();

    // ---- gather + max-edge using top-9 indices in si[0..8]
    if (threadIdx.x < CC) {
        const int c = threadIdx.x;
        const float* hb = d_h + (size_t)b * NN * CC;
        float hn = d_h[(size_t)row * CC + c];
        float mx = -INFINITY;
#pragma unroll
        for (int j = 0; j < KNB; j++)
            mx = fmaxf(mx, hb[(size_t)si[j] * CC + c] - hn);
        d_gbuf[(size_t)row * CC2 + c]      = hn;
        d_gbuf[(size_t)row * CC2 + CC + c] = mx;
    }
}

// ---------------- transpose (B,N,C)->(B,C,N) + residual ---------------------
__global__ void out_kernel(const float* __restrict__ x, float* __restrict__ out) {
    __shared__ float tile[32][33];
    const int b = blockIdx.z;
    const int n0 = blockIdx.x * 32, c0 = blockIdx.y * 32;
    const int tx = threadIdx.x, ty = threadIdx.y;
#pragma unroll
    for (int i = 0; i < 32; i += 8)
        tile[ty + i][tx] = d_obuf[((size_t)b * NN + n0 + ty + i) * CC + c0 + tx];
    __syncthreads();
#pragma unroll
    for (int i = 0; i < 32; i += 8) {
        int c = c0 + ty + i, n = n0 + tx;
        size_t o = ((size_t)b * CC + c) * NN + n;
        out[o] = tile[tx][ty + i] + x[o];
    }
}

// ---------------- launch ----------------------------------------------------
extern "C" void kernel_launch(void* const* d_in, const int* in_sizes, int n_in,
                              void* d_out, int out_size)
{
    (void)in_sizes; (void)n_in; (void)out_size;
    const float* x     = (const float*)d_in[0];
    const float* fc1_w = (const float*)d_in[1];
    const float* fc1_b = (const float*)d_in[2];
    const float* bn1_g = (const float*)d_in[3];
    const float* bn1_b = (const float*)d_in[4];
    const float* bn1_m = (const float*)d_in[5];
    const float* bn1_v = (const float*)d_in[6];
    const float* gc_w  = (const float*)d_in[7];
    const float* gc_b  = (const float*)d_in[8];
    const float* bng_g = (const float*)d_in[9];
    const float* bng_b = (const float*)d_in[10];
    const float* bng_m = (const float*)d_in[11];
    const float* bng_v = (const float*)d_in[12];
    const float* fc2_w = (const float*)d_in[13];
    const float* fc2_b = (const float*)d_in[14];
    const float* bn2_g = (const float*)d_in[15];
    const float* bn2_b = (const float*)d_in[16];
    const float* bn2_m = (const float*)d_in[17];
    const float* bn2_v = (const float*)d_in[18];
    float* out = (float*)d_out;

    // 1: fc1 + bn1 -> h
    gemm_kernel<0><<<dim3(2, 25, BB), 256>>>(x, fc1_w, fc1_b, bn1_g, bn1_b, bn1_m, bn1_v);
    // 2: normalize rows -> xn, sq
    norm_kernel<<<BB * NN, 64>>>();
    // 3: positional embedding (K-major)
    pe_kernel<<<(NN * CC + 255) / 256, 256>>>();
    // 4: rel = (-2/C) peT^T peT (symmetric upper-tri + mirror)  [ncu slot]
    gemm_kernel<1><<<dim3(25, 25, 1), 256>>>(nullptr, nullptr, nullptr, nullptr, nullptr, nullptr, nullptr);
    // 5: xn -> xnT (K-major)
    xnt_kernel<<<dim3(98, 6, BB), dim3(32, 8)>>>();
    // 6: dist = sq[m] - 2 xn.xn^T + rel  (dominant GEMM, symmetric dot)
    gemm_kernel<2><<<dim3(25, 25, BB), 256>>>(nullptr, nullptr, nullptr, nullptr, nullptr, nullptr, nullptr);
    // 7: fused top-9 + gather/max-edge -> g = [h, d]
    topk_gather_kernel<<<BB * NN, 256>>>();
    // 8: grouped conv + bn + gelu -> y
    gemm_kernel<3><<<dim3(1, 25, BB * 4), 256>>>(nullptr, gc_w, gc_b, bng_g, bng_b, bng_m, bng_v);
    // 9: fc2 + bn2 -> o
    gemm_kernel<4><<<dim3(2, 196, 1), 256>>>(nullptr, fc2_w, fc2_b, bn2_g, bn2_b, bn2_m, bn2_v);
    // 10: transpose + residual -> out
    out_kernel<<<dim3(98, 6, BB), dim3(32, 8)>>>(x, out);
}